// round 1
// baseline (speedup 1.0000x reference)
#include <cuda_runtime.h>
#include <cuda_bf16.h>

#define HH 128
#define WWID 128
#define NBATCH 8
#define CIN 64
#define HW (HH*WWID)

// Scratch (allocation-free rule: __device__ globals)
__device__ float g_buf0[NBATCH * CIN * HW];   // 33.5 MB
__device__ float g_buf1[NBATCH * CIN * HW];   // 33.5 MB
__device__ float g_bcoef[NBATCH * 54 * HW];   // 28 MB  (N, 6 feat, 9 taps, H, W)

// ---------------------------------------------------------------------------
// conv3x3 (SAME) + BN(inference) + tanh, Cin=64 -> Cout=64
// Block: 256 threads = 16 (x) * 4 (y-quad) * 4 (oc-group). Tile 16x16 pixels.
// Each thread: 4 pixels (rows tyq + 4p) x 16 output channels.
// LDS/FMA ratio per ic per thread: (36 + 144)/576 ~ 0.31 -> FFMA-issue bound.
// ---------------------------------------------------------------------------
__global__ __launch_bounds__(256) void conv_bn_tanh64(
    const float* __restrict__ in, float* __restrict__ out,
    const float* __restrict__ wgt, const float* __restrict__ bias,
    const float* __restrict__ gam, const float* __restrict__ bet,
    const float* __restrict__ mea, const float* __restrict__ var)
{
    __shared__ float tile[18 * 18];
    __shared__ float wsm[64 * 9];
    __shared__ float s_scale[64], s_shift[64];

    const int tid = threadIdx.x;
    const int tx  = tid & 15;
    const int tyq = (tid >> 4) & 3;
    const int grp = tid >> 6;
    const int bx = blockIdx.x << 4, by = blockIdx.y << 4, b = blockIdx.z;

    if (tid < 64) {
        float sc = gam[tid] * rsqrtf(var[tid] + 1e-5f);
        s_scale[tid] = sc;
        s_shift[tid] = (bias[tid] - mea[tid]) * sc + bet[tid];
    }

    float acc[4][16];
    #pragma unroll
    for (int p = 0; p < 4; p++)
        #pragma unroll
        for (int o = 0; o < 16; o++) acc[p][o] = 0.f;

    const float* inb = in + (size_t)b * CIN * HW;

    for (int ic = 0; ic < CIN; ic++) {
        __syncthreads();
        // input tile 18x18 (zero-padded at image border)
        for (int i = tid; i < 324; i += 256) {
            int r = i / 18, c = i - r * 18;
            int hh = by + r - 1, ww = bx + c - 1;
            float v = 0.f;
            if ((unsigned)hh < HH && (unsigned)ww < WWID)
                v = inb[ic * HW + hh * WWID + ww];
            tile[i] = v;
        }
        // weight slice for this ic: 64 oc x 9
        for (int i = tid; i < 576; i += 256) {
            int oc = i / 9, k = i - oc * 9;
            wsm[i] = wgt[oc * (CIN * 9) + ic * 9 + k];
        }
        __syncthreads();

        float vv[4][9];
        #pragma unroll
        for (int p = 0; p < 4; p++) {
            int r0 = p * 4 + tyq;
            #pragma unroll
            for (int dy = 0; dy < 3; dy++)
                #pragma unroll
                for (int dx = 0; dx < 3; dx++)
                    vv[p][dy * 3 + dx] = tile[(r0 + dy) * 18 + tx + dx];
        }
        const float* wg = wsm + grp * 16 * 9;
        #pragma unroll
        for (int o = 0; o < 16; o++) {
            float wr[9];
            #pragma unroll
            for (int k = 0; k < 9; k++) wr[k] = wg[o * 9 + k];
            #pragma unroll
            for (int p = 0; p < 4; p++)
                #pragma unroll
                for (int k = 0; k < 9; k++)
                    acc[p][o] = fmaf(vv[p][k], wr[k], acc[p][o]);
        }
    }

    float* outb = out + (size_t)b * CIN * HW;
    #pragma unroll
    for (int o = 0; o < 16; o++) {
        int oc = grp * 16 + o;
        float sc = s_scale[oc], sh = s_shift[oc];
        #pragma unroll
        for (int p = 0; p < 4; p++) {
            int h = by + p * 4 + tyq;
            outb[oc * HW + h * WWID + bx + tx] = tanhf(acc[p][o] * sc + sh);
        }
    }
}

// ---------------------------------------------------------------------------
// Last layer: conv3x3+BN+tanh 64 -> 36, fused with bcoef einsum:
//   bcoef[b,m,l,h,w] = sum_k tanh_out[b, m*6+k, h,w] * bases[k,l]
// Same tiling; grp handles 9 oc (4*9 = 36). Phase 2 via smem.
// ---------------------------------------------------------------------------
__global__ __launch_bounds__(256) void conv_last_bcoef(
    const float* __restrict__ in, float* __restrict__ bco,
    const float* __restrict__ wgt, const float* __restrict__ bias,
    const float* __restrict__ gam, const float* __restrict__ bet,
    const float* __restrict__ mea, const float* __restrict__ var,
    const float* __restrict__ bases)
{
    __shared__ float tile[18 * 18];
    __shared__ float wsm[36 * 9];
    __shared__ float s_scale[36], s_shift[36];
    __shared__ float s_bases[54];
    __shared__ float hs[256 * 37];   // 36 ch per pixel, pad 37 (odd stride, conflict-free)

    const int tid = threadIdx.x;
    const int tx  = tid & 15;
    const int tyq = (tid >> 4) & 3;
    const int grp = tid >> 6;
    const int bx = blockIdx.x << 4, by = blockIdx.y << 4, b = blockIdx.z;

    if (tid < 36) {
        float sc = gam[tid] * rsqrtf(var[tid] + 1e-5f);
        s_scale[tid] = sc;
        s_shift[tid] = (bias[tid] - mea[tid]) * sc + bet[tid];
    }
    if (tid < 54) s_bases[tid] = bases[tid];

    float acc[4][9];
    #pragma unroll
    for (int p = 0; p < 4; p++)
        #pragma unroll
        for (int o = 0; o < 9; o++) acc[p][o] = 0.f;

    const float* inb = in + (size_t)b * CIN * HW;

    for (int ic = 0; ic < CIN; ic++) {
        __syncthreads();
        for (int i = tid; i < 324; i += 256) {
            int r = i / 18, c = i - r * 18;
            int hh = by + r - 1, ww = bx + c - 1;
            float v = 0.f;
            if ((unsigned)hh < HH && (unsigned)ww < WWID)
                v = inb[ic * HW + hh * WWID + ww];
            tile[i] = v;
        }
        for (int i = tid; i < 324; i += 256) {
            int oc = i / 9, k = i - oc * 9;
            wsm[i] = wgt[oc * (CIN * 9) + ic * 9 + k];
        }
        __syncthreads();

        float vv[4][9];
        #pragma unroll
        for (int p = 0; p < 4; p++) {
            int r0 = p * 4 + tyq;
            #pragma unroll
            for (int dy = 0; dy < 3; dy++)
                #pragma unroll
                for (int dx = 0; dx < 3; dx++)
                    vv[p][dy * 3 + dx] = tile[(r0 + dy) * 18 + tx + dx];
        }
        const float* wg = wsm + grp * 9 * 9;
        #pragma unroll
        for (int o = 0; o < 9; o++) {
            float wr[9];
            #pragma unroll
            for (int k = 0; k < 9; k++) wr[k] = wg[o * 9 + k];
            #pragma unroll
            for (int p = 0; p < 4; p++)
                #pragma unroll
                for (int k = 0; k < 9; k++)
                    acc[p][o] = fmaf(vv[p][k], wr[k], acc[p][o]);
        }
    }

    // BN + tanh -> smem (pixel-major, padded)
    #pragma unroll
    for (int o = 0; o < 9; o++) {
        int oc = grp * 9 + o;
        float sc = s_scale[oc], sh = s_shift[oc];
        #pragma unroll
        for (int p = 0; p < 4; p++) {
            int pix = (p * 4 + tyq) * 16 + tx;
            hs[pix * 37 + oc] = tanhf(acc[p][o] * sc + sh);
        }
    }
    __syncthreads();

    // Phase 2: each thread owns one pixel, computes bcoef[6][9] and stores.
    const int pix = tid;
    const int h = by + (pix >> 4), w = bx + (pix & 15);
    const float* hp = &hs[pix * 37];
    #pragma unroll
    for (int m = 0; m < 6; m++) {
        float hm[6];
        #pragma unroll
        for (int k = 0; k < 6; k++) hm[k] = hp[m * 6 + k];
        #pragma unroll
        for (int l = 0; l < 9; l++) {
            float s = 0.f;
            #pragma unroll
            for (int k = 0; k < 6; k++) s = fmaf(hm[k], s_bases[k * 9 + l], s);
            bco[((size_t)(b * 6 + m) * 9 + l) * HW + h * WWID + w] = s;
        }
    }
}

// ---------------------------------------------------------------------------
// Dynamic conv: out[b, c*6+m, h, w] = sum_l bcoef[b,m,l,h,w] * x[b,c,h+dy,w+dx]
// Bandwidth bound (201 MB write). One thread per pixel, loop over c.
// ---------------------------------------------------------------------------
__global__ __launch_bounds__(256) void dynconv(
    const float* __restrict__ x, const float* __restrict__ bco,
    float* __restrict__ out)
{
    const int b = blockIdx.y;
    const int pix = blockIdx.x * 256 + threadIdx.x;
    const int h = pix >> 7, w = pix & 127;

    float bc[54];
    const float* bcb = bco + (size_t)b * 54 * HW + pix;
    #pragma unroll
    for (int i = 0; i < 54; i++) bc[i] = bcb[(size_t)i * HW];

    bool ok[9]; int off[9];
    #pragma unroll
    for (int dy = 0; dy < 3; dy++)
        #pragma unroll
        for (int dx = 0; dx < 3; dx++) {
            int k = dy * 3 + dx;
            int hh = h + dy - 1, ww = w + dx - 1;
            ok[k] = ((unsigned)hh < HH) && ((unsigned)ww < WWID);
            off[k] = hh * WWID + ww;
        }

    const float* xb = x + (size_t)b * CIN * HW;
    float* ob = out + (size_t)b * (CIN * 6) * HW + pix;

    for (int c = 0; c < CIN; c++) {
        const float* xc = xb + c * HW;
        float v[9];
        #pragma unroll
        for (int k = 0; k < 9; k++) v[k] = ok[k] ? __ldg(xc + off[k]) : 0.f;
        #pragma unroll
        for (int m = 0; m < 6; m++) {
            float s = 0.f;
            #pragma unroll
            for (int k = 0; k < 9; k++) s = fmaf(bc[m * 9 + k], v[k], s);
            ob[(size_t)(c * 6 + m) * HW] = s;
        }
    }
}

// ---------------------------------------------------------------------------
extern "C" void kernel_launch(void* const* d_in, const int* in_sizes, int n_in,
                              void* d_out, int out_size) {
    const float* x    = (const float*)d_in[0];
    const float* w0   = (const float*)d_in[1];
    const float* b0   = (const float*)d_in[2];
    const float* g0   = (const float*)d_in[3];
    const float* be0  = (const float*)d_in[4];
    const float* m0   = (const float*)d_in[5];
    const float* v0   = (const float*)d_in[6];
    const float* wm   = (const float*)d_in[7];
    const float* bm   = (const float*)d_in[8];
    const float* gm   = (const float*)d_in[9];
    const float* bem  = (const float*)d_in[10];
    const float* mm   = (const float*)d_in[11];
    const float* vm   = (const float*)d_in[12];
    const float* wl   = (const float*)d_in[13];
    const float* bl   = (const float*)d_in[14];
    const float* gl   = (const float*)d_in[15];
    const float* bel  = (const float*)d_in[16];
    const float* ml   = (const float*)d_in[17];
    const float* vl   = (const float*)d_in[18];
    const float* bases= (const float*)d_in[19];

    float *buf0, *buf1, *bco;
    cudaGetSymbolAddress((void**)&buf0, g_buf0);
    cudaGetSymbolAddress((void**)&buf1, g_buf1);
    cudaGetSymbolAddress((void**)&bco,  g_bcoef);

    dim3 blk(256);
    dim3 grd(WWID / 16, HH / 16, NBATCH);

    // Layer 0: x -> buf0
    conv_bn_tanh64<<<grd, blk>>>(x, buf0, w0, b0, g0, be0, m0, v0);

    // Mid layers 1..5, ping-pong
    float* bufs[2] = { buf0, buf1 };
    for (int i = 0; i < 5; i++) {
        const float* src = bufs[i & 1];
        float* dst = bufs[(i + 1) & 1];
        conv_bn_tanh64<<<grd, blk>>>(src, dst,
            wm + (size_t)i * 64 * 64 * 9, bm + i * 64,
            gm + i * 64, bem + i * 64, mm + i * 64, vm + i * 64);
    }
    // After 5 mid layers result is in bufs[5&1] = buf1
    conv_last_bcoef<<<grd, blk>>>(buf1, bco, wl, bl, gl, bel, ml, vl, bases);

    dim3 grd2(HW / 256, NBATCH);
    dynconv<<<grd2, blk>>>(x, bco, (float*)d_out);
}

// round 3
// speedup vs baseline: 1.1861x; 1.1861x over previous
#include <cuda_runtime.h>
#include <cuda_bf16.h>

#define HH 128
#define WWID 128
#define NBATCH 8
#define CIN 64
#define HW (HH*WWID)

// Scratch (allocation-free rule: __device__ globals)
__device__ float g_buf0[NBATCH * CIN * HW];
__device__ float g_buf1[NBATCH * CIN * HW];
__device__ float g_bcoef[NBATCH * 54 * HW];

typedef unsigned long long ull;

__device__ __forceinline__ ull ffma2(ull a, ull b, ull c) {
    ull d;
    asm("fma.rn.f32x2 %0, %1, %2, %3;" : "=l"(d) : "l"(a), "l"(b), "l"(c));
    return d;
}
__device__ __forceinline__ ull pack2(float a, float b) {
    ull r;
    asm("mov.b64 %0, {%1, %2};" : "=l"(r) : "f"(a), "f"(b));
    return r;
}
__device__ __forceinline__ void unpack2(ull v, float& lo, float& hi) {
    asm("mov.b64 {%0, %1}, %2;" : "=f"(lo), "=f"(hi) : "l"(v));
}
__device__ __forceinline__ float tanh_fast(float x) {
    float a = fminf(fmaxf(x, -9.f), 9.f);
    float e = __expf(2.f * a);
    return __fdividef(e - 1.f, e + 1.f);
}

// ---------------------------------------------------------------------------
// conv3x3 (SAME) + BN + tanh, 64 -> 64, using packed fma.rn.f32x2.
// Block 256 = tx(16) * tyq(4) * grp(4). Tile 16x16 pixels.
// Thread: 4 consecutive rows (tyq*4 + p) x 16 oc (8 f32x2 pairs).
// Weights staged in smem transposed [k][oc] so oc-pairs are LDS.64 broadcast.
// 2 input channels per barrier stage.
// ---------------------------------------------------------------------------
__global__ __launch_bounds__(256, 2) void conv_bn_tanh64(
    const float* __restrict__ in, float* __restrict__ out,
    const float* __restrict__ wgt, const float* __restrict__ bias,
    const float* __restrict__ gam, const float* __restrict__ bet,
    const float* __restrict__ mea, const float* __restrict__ var)
{
    __shared__ __align__(16) float tile[2][18 * 18];
    __shared__ __align__(16) float wk[2][9 * 64];   // [s][k*64 + oc]
    __shared__ float s_scale[64], s_shift[64];

    const int tid = threadIdx.x;
    const int tx  = tid & 15;
    const int tyq = (tid >> 4) & 3;
    const int grp = tid >> 6;
    const int bx = blockIdx.x << 4, by = blockIdx.y << 4, b = blockIdx.z;
    const int r0 = tyq * 4;

    if (tid < 64) {
        float sc = gam[tid] * rsqrtf(var[tid] + 1e-5f);
        s_scale[tid] = sc;
        s_shift[tid] = (bias[tid] - mea[tid]) * sc + bet[tid];
    }

    ull acc[4][8];
    #pragma unroll
    for (int p = 0; p < 4; p++)
        #pragma unroll
        for (int o = 0; o < 8; o++) acc[p][o] = 0ull;

    const float* inb = in + (size_t)b * CIN * HW;

    for (int ic0 = 0; ic0 < CIN; ic0 += 2) {
        __syncthreads();
        // input tiles for ic0, ic0+1 (18x18 each, zero-padded halo)
        for (int i = tid; i < 648; i += 256) {
            int s = (i >= 324);
            int j = i - s * 324;
            int r = j / 18, c = j - r * 18;
            int hh = by + r - 1, ww = bx + c - 1;
            float v = 0.f;
            if ((unsigned)hh < HH && (unsigned)ww < WWID)
                v = inb[(ic0 + s) * HW + hh * WWID + ww];
            tile[s][j] = v;
        }
        // weights transposed into [k][oc]
        for (int i = tid; i < 1152; i += 256) {
            int oc = i / 18;
            int r = i - oc * 18;
            int s = r / 9, k = r - s * 9;
            wk[s][k * 64 + oc] = wgt[oc * (CIN * 9) + (ic0 + s) * 9 + k];
        }
        __syncthreads();

        #pragma unroll
        for (int s = 0; s < 2; s++) {
            // 6 rows x 3 cols of input covering the 4 pixels' taps
            float va[6][3];
            #pragma unroll
            for (int rr = 0; rr < 6; rr++)
                #pragma unroll
                for (int dx = 0; dx < 3; dx++)
                    va[rr][dx] = tile[s][(r0 + rr) * 18 + tx + dx];

            #pragma unroll
            for (int k = 0; k < 9; k++) {
                const int dy = k / 3, dx = k - dy * 3;
                ull wp[8];
                const ull* wrow = (const ull*)&wk[s][k * 64 + grp * 16];
                #pragma unroll
                for (int o = 0; o < 8; o++) wp[o] = wrow[o];
                #pragma unroll
                for (int p = 0; p < 4; p++) {
                    ull v2 = pack2(va[p + dy][dx], va[p + dy][dx]);
                    #pragma unroll
                    for (int o = 0; o < 8; o++)
                        acc[p][o] = ffma2(v2, wp[o], acc[p][o]);
                }
            }
        }
    }

    float* outb = out + (size_t)b * CIN * HW;
    #pragma unroll
    for (int o = 0; o < 8; o++) {
        int oc0 = grp * 16 + 2 * o;
        float sc0 = s_scale[oc0],     sh0 = s_shift[oc0];
        float sc1 = s_scale[oc0 + 1], sh1 = s_shift[oc0 + 1];
        #pragma unroll
        for (int p = 0; p < 4; p++) {
            float lo, hi;
            unpack2(acc[p][o], lo, hi);
            int h = by + r0 + p;
            outb[(size_t)oc0 * HW + h * WWID + bx + tx]       = tanh_fast(lo * sc0 + sh0);
            outb[(size_t)(oc0 + 1) * HW + h * WWID + bx + tx] = tanh_fast(hi * sc1 + sh1);
        }
    }
}

// ---------------------------------------------------------------------------
// Last layer: conv3x3+BN+tanh 64 -> 36 fused with bcoef einsum.
// ---------------------------------------------------------------------------
__global__ __launch_bounds__(256) void conv_last_bcoef(
    const float* __restrict__ in, float* __restrict__ bco,
    const float* __restrict__ wgt, const float* __restrict__ bias,
    const float* __restrict__ gam, const float* __restrict__ bet,
    const float* __restrict__ mea, const float* __restrict__ var,
    const float* __restrict__ bases)
{
    __shared__ float tile[18 * 18];
    __shared__ float wsm[36 * 9];
    __shared__ float s_scale[36], s_shift[36];
    __shared__ float s_bases[54];
    __shared__ float hs[256 * 37];

    const int tid = threadIdx.x;
    const int tx  = tid & 15;
    const int tyq = (tid >> 4) & 3;
    const int grp = tid >> 6;
    const int bx = blockIdx.x << 4, by = blockIdx.y << 4, b = blockIdx.z;

    if (tid < 36) {
        float sc = gam[tid] * rsqrtf(var[tid] + 1e-5f);
        s_scale[tid] = sc;
        s_shift[tid] = (bias[tid] - mea[tid]) * sc + bet[tid];
    }
    if (tid < 54) s_bases[tid] = bases[tid];

    float acc[4][9];
    #pragma unroll
    for (int p = 0; p < 4; p++)
        #pragma unroll
        for (int o = 0; o < 9; o++) acc[p][o] = 0.f;

    const float* inb = in + (size_t)b * CIN * HW;

    for (int ic = 0; ic < CIN; ic++) {
        __syncthreads();
        for (int i = tid; i < 324; i += 256) {
            int r = i / 18, c = i - r * 18;
            int hh = by + r - 1, ww = bx + c - 1;
            float v = 0.f;
            if ((unsigned)hh < HH && (unsigned)ww < WWID)
                v = inb[ic * HW + hh * WWID + ww];
            tile[i] = v;
        }
        for (int i = tid; i < 324; i += 256) {
            int oc = i / 9, k = i - oc * 9;
            wsm[i] = wgt[oc * (CIN * 9) + ic * 9 + k];
        }
        __syncthreads();

        float vv[4][9];
        #pragma unroll
        for (int p = 0; p < 4; p++) {
            int rr0 = p * 4 + tyq;
            #pragma unroll
            for (int dy = 0; dy < 3; dy++)
                #pragma unroll
                for (int dx = 0; dx < 3; dx++)
                    vv[p][dy * 3 + dx] = tile[(rr0 + dy) * 18 + tx + dx];
        }
        const float* wg = wsm + grp * 9 * 9;
        #pragma unroll
        for (int o = 0; o < 9; o++) {
            float wr[9];
            #pragma unroll
            for (int k = 0; k < 9; k++) wr[k] = wg[o * 9 + k];
            #pragma unroll
            for (int p = 0; p < 4; p++)
                #pragma unroll
                for (int k = 0; k < 9; k++)
                    acc[p][o] = fmaf(vv[p][k], wr[k], acc[p][o]);
        }
    }

    #pragma unroll
    for (int o = 0; o < 9; o++) {
        int oc = grp * 9 + o;
        float sc = s_scale[oc], sh = s_shift[oc];
        #pragma unroll
        for (int p = 0; p < 4; p++) {
            int pix = (p * 4 + tyq) * 16 + tx;
            hs[pix * 37 + oc] = tanh_fast(acc[p][o] * sc + sh);
        }
    }
    __syncthreads();

    const int pix = tid;
    const int h = by + (pix >> 4), w = bx + (pix & 15);
    const float* hp = &hs[pix * 37];
    #pragma unroll
    for (int m = 0; m < 6; m++) {
        float hm[6];
        #pragma unroll
        for (int k = 0; k < 6; k++) hm[k] = hp[m * 6 + k];
        #pragma unroll
        for (int l = 0; l < 9; l++) {
            float s = 0.f;
            #pragma unroll
            for (int k = 0; k < 6; k++) s = fmaf(hm[k], s_bases[k * 9 + l], s);
            bco[((size_t)(b * 6 + m) * 9 + l) * HW + h * WWID + w] = s;
        }
    }
}

// ---------------------------------------------------------------------------
// Dynamic conv: out[b, c*6+m, h, w] = sum_l bcoef[b,m,l,h,w] * x_patch[l]
// ---------------------------------------------------------------------------
__global__ __launch_bounds__(256) void dynconv(
    const float* __restrict__ x, const float* __restrict__ bco,
    float* __restrict__ out)
{
    const int b = blockIdx.y;
    const int pix = blockIdx.x * 256 + threadIdx.x;
    const int h = pix >> 7, w = pix & 127;

    float bc[54];
    const float* bcb = bco + (size_t)b * 54 * HW + pix;
    #pragma unroll
    for (int i = 0; i < 54; i++) bc[i] = bcb[(size_t)i * HW];

    bool ok[9]; int off[9];
    #pragma unroll
    for (int dy = 0; dy < 3; dy++)
        #pragma unroll
        for (int dx = 0; dx < 3; dx++) {
            int k = dy * 3 + dx;
            int hh = h + dy - 1, ww = w + dx - 1;
            ok[k] = ((unsigned)hh < HH) && ((unsigned)ww < WWID);
            off[k] = hh * WWID + ww;
        }

    const float* xb = x + (size_t)b * CIN * HW;
    float* ob = out + (size_t)b * (CIN * 6) * HW + pix;

    for (int c = 0; c < CIN; c++) {
        const float* xc = xb + c * HW;
        float v[9];
        #pragma unroll
        for (int k = 0; k < 9; k++) v[k] = ok[k] ? __ldg(xc + off[k]) : 0.f;
        #pragma unroll
        for (int m = 0; m < 6; m++) {
            float s = 0.f;
            #pragma unroll
            for (int k = 0; k < 9; k++) s = fmaf(bc[m * 9 + k], v[k], s);
            ob[(size_t)(c * 6 + m) * HW] = s;
        }
    }
}

// ---------------------------------------------------------------------------
extern "C" void kernel_launch(void* const* d_in, const int* in_sizes, int n_in,
                              void* d_out, int out_size) {
    const float* x    = (const float*)d_in[0];
    const float* w0   = (const float*)d_in[1];
    const float* b0   = (const float*)d_in[2];
    const float* g0   = (const float*)d_in[3];
    const float* be0  = (const float*)d_in[4];
    const float* m0   = (const float*)d_in[5];
    const float* v0   = (const float*)d_in[6];
    const float* wm   = (const float*)d_in[7];
    const float* bm   = (const float*)d_in[8];
    const float* gm   = (const float*)d_in[9];
    const float* bem  = (const float*)d_in[10];
    const float* mm   = (const float*)d_in[11];
    const float* vm   = (const float*)d_in[12];
    const float* wl   = (const float*)d_in[13];
    const float* bl   = (const float*)d_in[14];
    const float* gl   = (const float*)d_in[15];
    const float* bel  = (const float*)d_in[16];
    const float* ml   = (const float*)d_in[17];
    const float* vl   = (const float*)d_in[18];
    const float* bases= (const float*)d_in[19];

    float *buf0, *buf1, *bco;
    cudaGetSymbolAddress((void**)&buf0, g_buf0);
    cudaGetSymbolAddress((void**)&buf1, g_buf1);
    cudaGetSymbolAddress((void**)&bco,  g_bcoef);

    dim3 blk(256);
    dim3 grd(WWID / 16, HH / 16, NBATCH);

    conv_bn_tanh64<<<grd, blk>>>(x, buf0, w0, b0, g0, be0, m0, v0);

    float* bufs[2] = { buf0, buf1 };
    for (int i = 0; i < 5; i++) {
        const float* src = bufs[i & 1];
        float* dst = bufs[(i + 1) & 1];
        conv_bn_tanh64<<<grd, blk>>>(src, dst,
            wm + (size_t)i * 64 * 64 * 9, bm + i * 64,
            gm + i * 64, bem + i * 64, mm + i * 64, vm + i * 64);
    }
    conv_last_bcoef<<<grd, blk>>>(buf1, bco, wl, bl, gl, bel, ml, vl, bases);

    dim3 grd2(HW / 256, NBATCH);
    dynconv<<<grd2, blk>>>(x, bco, (float*)d_out);
}

// round 4
// speedup vs baseline: 1.5188x; 1.2806x over previous
#include <cuda_runtime.h>
#include <cuda_bf16.h>

#define HH 128
#define WWID 128
#define NBATCH 8
#define CIN 64
#define HW (HH*WWID)
#define STAGE_IC 4
#define NSTAGES (CIN / STAGE_IC)   // 16

// Scratch (allocation-free rule: __device__ globals)
__device__ float g_buf0[NBATCH * CIN * HW];
__device__ float g_buf1[NBATCH * CIN * HW];
__device__ float g_bcoef[NBATCH * 54 * HW];
__device__ float g_wT[6 * CIN * 9 * 64];   // [l][ic][k][oc], BN-scale folded
__device__ float g_shiftT[6 * 64];

typedef unsigned long long ull;

__device__ __forceinline__ ull ffma2(ull a, ull b, ull c) {
    ull d;
    asm("fma.rn.f32x2 %0, %1, %2, %3;" : "=l"(d) : "l"(a), "l"(b), "l"(c));
    return d;
}
__device__ __forceinline__ ull pack2(float a, float b) {
    ull r;
    asm("mov.b64 %0, {%1, %2};" : "=l"(r) : "f"(a), "f"(b));
    return r;
}
__device__ __forceinline__ void unpack2(ull v, float& lo, float& hi) {
    asm("mov.b64 {%0, %1}, %2;" : "=f"(lo), "=f"(hi) : "l"(v));
}
__device__ __forceinline__ float tanh_fast(float x) {
    float a = fminf(fmaxf(x, -9.f), 9.f);
    float e = __expf(2.f * a);
    return __fdividef(e - 1.f, e + 1.f);
}
__device__ __forceinline__ void cp4z(float* dst, const float* src, bool ok) {
    unsigned d = (unsigned)__cvta_generic_to_shared(dst);
    int sz = ok ? 4 : 0;
    asm volatile("cp.async.ca.shared.global [%0], [%1], 4, %2;" :: "r"(d), "l"(src), "r"(sz));
}
__device__ __forceinline__ void cp16(void* dst, const void* src) {
    unsigned d = (unsigned)__cvta_generic_to_shared(dst);
    asm volatile("cp.async.cg.shared.global [%0], [%1], 16;" :: "r"(d), "l"(src));
}

// ---------------------------------------------------------------------------
// Prep: fold BN scale into weights, transpose to [ic][k][oc]; compute shift.
// ---------------------------------------------------------------------------
__global__ void prep_weights(
    const float* __restrict__ w0, const float* __restrict__ b0,
    const float* __restrict__ g0, const float* __restrict__ be0,
    const float* __restrict__ m0, const float* __restrict__ v0,
    const float* __restrict__ wm, const float* __restrict__ bm,
    const float* __restrict__ gm, const float* __restrict__ bem,
    const float* __restrict__ mm, const float* __restrict__ vm,
    float* __restrict__ wT, float* __restrict__ shiftT)
{
    const int l = blockIdx.y;   // 0..5
    const int ic = blockIdx.x;  // 0..63
    const float *w, *bb, *g, *be, *m, *v;
    if (l == 0) { w = w0; bb = b0; g = g0; be = be0; m = m0; v = v0; }
    else {
        int i = l - 1;
        w = wm + (size_t)i * 64 * 64 * 9; bb = bm + i * 64; g = gm + i * 64;
        be = bem + i * 64; m = mm + i * 64; v = vm + i * 64;
    }
    for (int e = threadIdx.x; e < 576; e += blockDim.x) {
        int k = e >> 6, oc = e & 63;
        float sc = g[oc] * rsqrtf(v[oc] + 1e-5f);
        wT[(((size_t)l * 64 + ic) * 9 + k) * 64 + oc] =
            w[((size_t)oc * 64 + ic) * 9 + k] * sc;
    }
    if (ic == 0) {
        for (int oc = threadIdx.x; oc < 64; oc += blockDim.x) {
            float sc = g[oc] * rsqrtf(v[oc] + 1e-5f);
            shiftT[l * 64 + oc] = (bb[oc] - m[oc]) * sc + be[oc];
        }
    }
}

// ---------------------------------------------------------------------------
// conv3x3 + folded BN + tanh, 64->64, FFMA2 math, cp.async double-buffered.
// Block 256 = tx(16) * tyq(4) * grp(4); tile 16x16 pixels.
// Thread: 4 consecutive rows x 16 oc (8 f32x2 pairs).
// ---------------------------------------------------------------------------
__global__ __launch_bounds__(256, 2) void conv_bn_tanh64(
    const float* __restrict__ in, float* __restrict__ out,
    const float* __restrict__ wT, const float* __restrict__ shiftT)
{
    __shared__ __align__(16) float tile[2][STAGE_IC][324];
    __shared__ __align__(16) float wk[2][STAGE_IC * 576];
    __shared__ float s_shift[64];

    const int tid = threadIdx.x;
    const int tx  = tid & 15;
    const int tyq = (tid >> 4) & 3;
    const int grp = tid >> 6;
    const int bx = blockIdx.x << 4, by = blockIdx.y << 4, b = blockIdx.z;
    const int r0 = tyq * 4;

    if (tid < 64) s_shift[tid] = shiftT[tid];

    const float* inb = in + (size_t)b * CIN * HW;

    // ---- async stage copy: stage s (4 ics) into buffer buf ----
    auto issue_stage = [&](int s, int buf) {
        const int ic0 = s * STAGE_IC;
        #pragma unroll 1
        for (int i = tid; i < STAGE_IC * 324; i += 256) {
            int ic = i / 324, j = i - ic * 324;
            int r = j / 18, c = j - r * 18;
            int hh = by + r - 1, ww = bx + c - 1;
            bool ok = ((unsigned)hh < HH) && ((unsigned)ww < WWID);
            const float* src = ok ? (inb + (size_t)(ic0 + ic) * HW + hh * WWID + ww) : inb;
            cp4z(&tile[buf][ic][j], src, ok);
        }
        const float4* wsrc = (const float4*)(wT + (size_t)ic0 * 576);
        float4* wdst = (float4*)wk[buf];
        #pragma unroll 1
        for (int i = tid; i < STAGE_IC * 576 / 4; i += 256)
            cp16(&wdst[i], &wsrc[i]);
        asm volatile("cp.async.commit_group;" ::: "memory");
    };

    ull acc[4][8];
    #pragma unroll
    for (int p = 0; p < 4; p++)
        #pragma unroll
        for (int o = 0; o < 8; o++) acc[p][o] = 0ull;

    issue_stage(0, 0);
    issue_stage(1, 1);

    for (int s = 0; s < NSTAGES; s++) {
        asm volatile("cp.async.wait_group 1;" ::: "memory");
        __syncthreads();
        const int buf = s & 1;

        #pragma unroll
        for (int ic = 0; ic < STAGE_IC; ic++) {
            float va[6][3];
            #pragma unroll
            for (int rr = 0; rr < 6; rr++)
                #pragma unroll
                for (int dx = 0; dx < 3; dx++)
                    va[rr][dx] = tile[buf][ic][(r0 + rr) * 18 + tx + dx];

            const float* wbase = &wk[buf][ic * 576];
            #pragma unroll
            for (int k = 0; k < 9; k++) {
                const int dy = k / 3, dx = k - dy * 3;
                ull wp[8];
                const ull* wrow = (const ull*)(wbase + k * 64 + grp * 16);
                #pragma unroll
                for (int o = 0; o < 8; o++) wp[o] = wrow[o];
                #pragma unroll
                for (int p = 0; p < 4; p++) {
                    ull v2 = pack2(va[p + dy][dx], va[p + dy][dx]);
                    #pragma unroll
                    for (int o = 0; o < 8; o++)
                        acc[p][o] = ffma2(v2, wp[o], acc[p][o]);
                }
            }
        }

        __syncthreads();
        if (s + 2 < NSTAGES) issue_stage(s + 2, buf);
        else asm volatile("cp.async.commit_group;" ::: "memory");
    }

    float* outb = out + (size_t)b * CIN * HW;
    #pragma unroll
    for (int o = 0; o < 8; o++) {
        int oc0 = grp * 16 + 2 * o;
        float sh0 = s_shift[oc0], sh1 = s_shift[oc0 + 1];
        #pragma unroll
        for (int p = 0; p < 4; p++) {
            float lo, hi;
            unpack2(acc[p][o], lo, hi);
            int h = by + r0 + p;
            outb[(size_t)oc0 * HW + h * WWID + bx + tx]       = tanh_fast(lo + sh0);
            outb[(size_t)(oc0 + 1) * HW + h * WWID + bx + tx] = tanh_fast(hi + sh1);
        }
    }
}

// ---------------------------------------------------------------------------
// Last layer: conv3x3+BN+tanh 64 -> 36 fused with bcoef einsum.
// ---------------------------------------------------------------------------
__global__ __launch_bounds__(256) void conv_last_bcoef(
    const float* __restrict__ in, float* __restrict__ bco,
    const float* __restrict__ wgt, const float* __restrict__ bias,
    const float* __restrict__ gam, const float* __restrict__ bet,
    const float* __restrict__ mea, const float* __restrict__ var,
    const float* __restrict__ bases)
{
    __shared__ float tile[18 * 18];
    __shared__ float wsm[36 * 9];
    __shared__ float s_scale[36], s_shift[36];
    __shared__ float s_bases[54];
    __shared__ float hs[256 * 37];

    const int tid = threadIdx.x;
    const int tx  = tid & 15;
    const int tyq = (tid >> 4) & 3;
    const int grp = tid >> 6;
    const int bx = blockIdx.x << 4, by = blockIdx.y << 4, b = blockIdx.z;

    if (tid < 36) {
        float sc = gam[tid] * rsqrtf(var[tid] + 1e-5f);
        s_scale[tid] = sc;
        s_shift[tid] = (bias[tid] - mea[tid]) * sc + bet[tid];
    }
    if (tid < 54) s_bases[tid] = bases[tid];

    float acc[4][9];
    #pragma unroll
    for (int p = 0; p < 4; p++)
        #pragma unroll
        for (int o = 0; o < 9; o++) acc[p][o] = 0.f;

    const float* inb = in + (size_t)b * CIN * HW;

    for (int ic = 0; ic < CIN; ic++) {
        __syncthreads();
        for (int i = tid; i < 324; i += 256) {
            int r = i / 18, c = i - r * 18;
            int hh = by + r - 1, ww = bx + c - 1;
            float v = 0.f;
            if ((unsigned)hh < HH && (unsigned)ww < WWID)
                v = inb[ic * HW + hh * WWID + ww];
            tile[i] = v;
        }
        for (int i = tid; i < 324; i += 256) {
            int oc = i / 9, k = i - oc * 9;
            wsm[i] = wgt[oc * (CIN * 9) + ic * 9 + k];
        }
        __syncthreads();

        float vv[4][9];
        #pragma unroll
        for (int p = 0; p < 4; p++) {
            int rr0 = p * 4 + tyq;
            #pragma unroll
            for (int dy = 0; dy < 3; dy++)
                #pragma unroll
                for (int dx = 0; dx < 3; dx++)
                    vv[p][dy * 3 + dx] = tile[(rr0 + dy) * 18 + tx + dx];
        }
        const float* wg = wsm + grp * 9 * 9;
        #pragma unroll
        for (int o = 0; o < 9; o++) {
            float wr[9];
            #pragma unroll
            for (int k = 0; k < 9; k++) wr[k] = wg[o * 9 + k];
            #pragma unroll
            for (int p = 0; p < 4; p++)
                #pragma unroll
                for (int k = 0; k < 9; k++)
                    acc[p][o] = fmaf(vv[p][k], wr[k], acc[p][o]);
        }
    }

    #pragma unroll
    for (int o = 0; o < 9; o++) {
        int oc = grp * 9 + o;
        float sc = s_scale[oc], sh = s_shift[oc];
        #pragma unroll
        for (int p = 0; p < 4; p++) {
            int pix = (p * 4 + tyq) * 16 + tx;
            hs[pix * 37 + oc] = tanh_fast(acc[p][o] * sc + sh);
        }
    }
    __syncthreads();

    const int pix = tid;
    const int h = by + (pix >> 4), w = bx + (pix & 15);
    const float* hp = &hs[pix * 37];
    #pragma unroll
    for (int m = 0; m < 6; m++) {
        float hm[6];
        #pragma unroll
        for (int k = 0; k < 6; k++) hm[k] = hp[m * 6 + k];
        #pragma unroll
        for (int l = 0; l < 9; l++) {
            float s = 0.f;
            #pragma unroll
            for (int k = 0; k < 6; k++) s = fmaf(hm[k], s_bases[k * 9 + l], s);
            bco[((size_t)(b * 6 + m) * 9 + l) * HW + h * WWID + w] = s;
        }
    }
}

// ---------------------------------------------------------------------------
// Dynamic conv: out[b, c*6+m, h, w] = sum_l bcoef[b,m,l,h,w] * x_patch[l]
// ---------------------------------------------------------------------------
__global__ __launch_bounds__(256) void dynconv(
    const float* __restrict__ x, const float* __restrict__ bco,
    float* __restrict__ out)
{
    const int b = blockIdx.y;
    const int pix = blockIdx.x * 256 + threadIdx.x;
    const int h = pix >> 7, w = pix & 127;

    float bc[54];
    const float* bcb = bco + (size_t)b * 54 * HW + pix;
    #pragma unroll
    for (int i = 0; i < 54; i++) bc[i] = bcb[(size_t)i * HW];

    bool ok[9]; int off[9];
    #pragma unroll
    for (int dy = 0; dy < 3; dy++)
        #pragma unroll
        for (int dx = 0; dx < 3; dx++) {
            int k = dy * 3 + dx;
            int hh = h + dy - 1, ww = w + dx - 1;
            ok[k] = ((unsigned)hh < HH) && ((unsigned)ww < WWID);
            off[k] = hh * WWID + ww;
        }

    const float* xb = x + (size_t)b * CIN * HW;
    float* ob = out + (size_t)b * (CIN * 6) * HW + pix;

    for (int c = 0; c < CIN; c++) {
        const float* xc = xb + c * HW;
        float v[9];
        #pragma unroll
        for (int k = 0; k < 9; k++) v[k] = ok[k] ? __ldg(xc + off[k]) : 0.f;
        #pragma unroll
        for (int m = 0; m < 6; m++) {
            float s = 0.f;
            #pragma unroll
            for (int k = 0; k < 9; k++) s = fmaf(bc[m * 9 + k], v[k], s);
            ob[(size_t)(c * 6 + m) * HW] = s;
        }
    }
}

// ---------------------------------------------------------------------------
extern "C" void kernel_launch(void* const* d_in, const int* in_sizes, int n_in,
                              void* d_out, int out_size) {
    const float* x    = (const float*)d_in[0];
    const float* w0   = (const float*)d_in[1];
    const float* b0   = (const float*)d_in[2];
    const float* g0   = (const float*)d_in[3];
    const float* be0  = (const float*)d_in[4];
    const float* m0   = (const float*)d_in[5];
    const float* v0   = (const float*)d_in[6];
    const float* wm   = (const float*)d_in[7];
    const float* bm   = (const float*)d_in[8];
    const float* gm   = (const float*)d_in[9];
    const float* bem  = (const float*)d_in[10];
    const float* mm   = (const float*)d_in[11];
    const float* vm   = (const float*)d_in[12];
    const float* wl   = (const float*)d_in[13];
    const float* bl   = (const float*)d_in[14];
    const float* gl   = (const float*)d_in[15];
    const float* bel  = (const float*)d_in[16];
    const float* ml   = (const float*)d_in[17];
    const float* vl   = (const float*)d_in[18];
    const float* bases= (const float*)d_in[19];

    float *buf0, *buf1, *bco, *wT, *shiftT;
    cudaGetSymbolAddress((void**)&buf0, g_buf0);
    cudaGetSymbolAddress((void**)&buf1, g_buf1);
    cudaGetSymbolAddress((void**)&bco,  g_bcoef);
    cudaGetSymbolAddress((void**)&wT,   g_wT);
    cudaGetSymbolAddress((void**)&shiftT, g_shiftT);

    dim3 pgrd(64, 6);
    prep_weights<<<pgrd, 256>>>(w0, b0, g0, be0, m0, v0,
                                wm, bm, gm, bem, mm, vm, wT, shiftT);

    dim3 blk(256);
    dim3 grd(WWID / 16, HH / 16, NBATCH);

    conv_bn_tanh64<<<grd, blk>>>(x, buf0, wT, shiftT);

    float* bufs[2] = { buf0, buf1 };
    for (int i = 0; i < 5; i++) {
        const float* src = bufs[i & 1];
        float* dst = bufs[(i + 1) & 1];
        conv_bn_tanh64<<<grd, blk>>>(src, dst,
            wT + (size_t)(i + 1) * CIN * 9 * 64, shiftT + (i + 1) * 64);
    }
    conv_last_bcoef<<<grd, blk>>>(buf1, bco, wl, bl, gl, bel, ml, vl, bases);

    dim3 grd2(HW / 256, NBATCH);
    dynconv<<<grd2, blk>>>(x, bco, (float*)d_out);
}